// round 13
// baseline (speedup 1.0000x reference)
#include <cuda_runtime.h>
#include <cuda_fp16.h>
#include <cstdint>
#include <cstddef>

#define BATCH 4096
#define DIM   1024

// ---------------- scratch (static device memory) ----------------------------
__device__ __half g_wm16[6u * 1024u * 1024u];  // fp16 masked weights
__device__ __half g_x16 [BATCH * DIM];         // fp16 input copy
__device__ __half g_h1s [BATCH * DIM];
__device__ __half g_h2s [BATCH * DIM];
__device__ __half g_h1t [BATCH * DIM];
__device__ __half g_h2t [BATCH * DIM];
__device__ float  g_m   [BATCH * DIM];
__device__ float  g_a   [BATCH * DIM];
__device__ unsigned g_done[3][2][32];          // [layer done][branch][M-block]

// ---------------- helpers ---------------------------------------------------
__device__ __forceinline__ uint32_t smem_u32(const void* p) {
    uint32_t a;
    asm("{ .reg .u64 t; cvta.to.shared.u64 t, %1; cvt.u32.u64 %0, t; }" : "=r"(a) : "l"(p));
    return a;
}

__device__ __forceinline__ void ldm_x4(uint32_t& r0, uint32_t& r1, uint32_t& r2, uint32_t& r3,
                                       uint32_t addr) {
    asm volatile("ldmatrix.sync.aligned.m8n8.x4.shared.b16 {%0,%1,%2,%3}, [%4];"
                 : "=r"(r0), "=r"(r1), "=r"(r2), "=r"(r3) : "r"(addr));
}

__device__ __forceinline__ void mma_f16(float& d0, float& d1, float& d2, float& d3,
                                        uint32_t a0, uint32_t a1, uint32_t a2, uint32_t a3,
                                        uint32_t b0, uint32_t b1) {
    asm("mma.sync.aligned.m16n8k16.row.col.f32.f16.f16.f32 "
        "{%0,%1,%2,%3},{%4,%5,%6,%7},{%8,%9},{%0,%1,%2,%3};\n"
        : "+f"(d0), "+f"(d1), "+f"(d2), "+f"(d3)
        : "r"(a0), "r"(a1), "r"(a2), "r"(a3), "r"(b0), "r"(b1));
}

#define CP_ASYNC16(dst, src) \
    asm volatile("cp.async.cg.shared.global [%0], [%1], 16;" :: "r"(dst), "l"(src) : "memory")
#define CP_COMMIT() asm volatile("cp.async.commit_group;" ::: "memory")
#define CP_WAIT1()  asm volatile("cp.async.wait_group 1;" ::: "memory")

// ---------------- fused prep: masked weights (analytic masks) + x ------------
// mask_in [o,i] = (o%1023 >= i) ; mask_hid[o,i] = (o%1023 >= i%1023) ;
// mask_out[o,i] = (o-1 >= i%1023). Only GEMM-read regions are written:
// triangular (c4 < 32*(cb+1)) for all, wrap chunk (c4 >= 240) for slots 1,2,4,5.
__global__ void prep_fused(const float* __restrict__ sw1, const float* __restrict__ sw2,
                           const float* __restrict__ sw3, const float* __restrict__ tw1,
                           const float* __restrict__ tw2, const float* __restrict__ tw3,
                           const float* __restrict__ x,
                           __half* __restrict__ dst, __half* __restrict__ xdst) {
    const size_t WSZ = 1024u * 1024u;
    const int bid = blockIdx.x;
    if (bid >= 1024) {
        // ---- x conversion: 1 float4 per thread (max memory parallelism) ----
        int i = (bid - 1024) * 256 + threadIdx.x;
        float4 v = reinterpret_cast<const float4*>(x)[i];
        __half2* d2 = reinterpret_cast<__half2*>(xdst);
        d2[2 * i]     = __floats2half2_rn(v.x, v.y);
        d2[2 * i + 1] = __floats2half2_rn(v.z, v.w);
        return;
    }
    int i = bid * blockDim.x + threadIdx.x;   // over 262144 float4
    int o  = i >> 8;           // output row
    int c4 = i & 255;          // float4 column index
    int cb = o >> 7;
    bool tri  = (c4 < 32 * (cb + 1));
    bool wrap = (c4 >= 240);
    if (!tri && !wrap) return;

    const int col0 = c4 * 4;
    const int od = o % 1023;
    float mh[4], mo[4], mi[4];
#pragma unroll
    for (int k = 0; k < 4; ++k) {
        int col = col0 + k;
        int cm  = col % 1023;
        mi[k] = (od >= col)     ? 1.f : 0.f;
        mh[k] = (od >= cm)      ? 1.f : 0.f;
        mo[k] = ((o - 1) >= cm) ? 1.f : 0.f;
    }
#define DO_W(wp, mk, slot) { \
        float4 wv = reinterpret_cast<const float4*>(wp)[i]; \
        __half2* d2 = reinterpret_cast<__half2*>(dst + (slot) * WSZ); \
        d2[2 * i]     = __floats2half2_rn(wv.x * mk[0], wv.y * mk[1]); \
        d2[2 * i + 1] = __floats2half2_rn(wv.z * mk[2], wv.w * mk[3]); }
    if (tri) {
        DO_W(sw1, mi, 0); DO_W(tw1, mi, 3);
    }
    DO_W(sw2, mh, 1); DO_W(sw3, mo, 2);
    DO_W(tw2, mh, 4); DO_W(tw3, mo, 5);
#undef DO_W
}

// ---------------- single-launch 3-layer dual-branch GEMM + finale ------------
// Grid = (branch=2, M=32, zc=25); zc slowest. zc<24: layer = zc>>3, cb=7-(zc&7)
// (LPT within layer). zc==24: finale CTAs (dispatched last) — wait for both
// branches' layer-3 strip, then compute u=(x-m)*exp(-a) + logdet for 64 rows.
// Strip-local deps via g_done spin counters. fp16 in, fp32 acc. CTA tile
// 128x128, BK=64, 256 threads, warp tile 64x32, 3-stage cp.async (2 CTAs/SM).
#define ACT_TANH 0
#define ACT_RELU 1
#define ACT_NONE 2

#define NCH 16
#define STAGES 3
#define ROWB 144
#define STAGE_BYTES (256 * ROWB)
#define B_SMEM_OFF  (128 * ROWB)
#define GEMM_SMEM   (STAGES * STAGE_BYTES)   // 110592

__global__ __launch_bounds__(256, 2)
void gemm_made_kernel(const float* __restrict__ xf, const __half* __restrict__ x16,
                      __half* __restrict__ h1s, __half* __restrict__ h1t,
                      __half* __restrict__ h2s, __half* __restrict__ h2t,
                      const __half* __restrict__ wm,
                      const float* __restrict__ sb1, const float* __restrict__ sb2,
                      const float* __restrict__ sb3, const float* __restrict__ tb1,
                      const float* __restrict__ tb2, const float* __restrict__ tb3,
                      float* __restrict__ mbuf, float* __restrict__ abuf,
                      float* __restrict__ out) {
    extern __shared__ __align__(16) char smc[];
    const uint32_t sbase = smem_u32(smc);
    const size_t WSZ = 1024u * 1024u;

    const int b   = blockIdx.x;            // branch
    const int y   = blockIdx.y;            // M-block
    const int zc  = blockIdx.z;

    const int tid  = threadIdx.x;
    const int warp = tid >> 5;
    const int lane = tid & 31;

    if (zc == 24) {
        // ================= finale: u + logdet for rows [y*128+b*64, +64) ====
        if (tid == 0) {
            volatile unsigned* c0 = &g_done[2][0][y];
            volatile unsigned* c1 = &g_done[2][1][y];
            while (*c0 < 8u) { __nanosleep(128); }
            while (*c1 < 8u) { __nanosleep(128); }
            __threadfence();
        }
        __syncthreads();
        const int rbase = y * 128 + b * 64 + warp * 8;   // 8 warps x 8 rows
#pragma unroll 1
        for (int rr = 0; rr < 8; ++rr) {
            const int row = rbase + rr;
            const float4* ar = reinterpret_cast<const float4*>(abuf + (size_t)row * DIM);
            const float4* mr = reinterpret_cast<const float4*>(mbuf + (size_t)row * DIM);
            const float4* xr = reinterpret_cast<const float4*>(xf   + (size_t)row * DIM);
            float4*       ur = reinterpret_cast<float4*>(out + (size_t)row * DIM);
            float s = 0.f;
#pragma unroll
            for (int k = 0; k < 8; ++k) {
                int idx = lane + 32 * k;
                float4 av = ar[idx];
                float4 mv = mr[idx];
                float4 xv = xr[idx];
                float4 uv;
                uv.x = (xv.x - mv.x) * expf(-av.x);
                uv.y = (xv.y - mv.y) * expf(-av.y);
                uv.z = (xv.z - mv.z) * expf(-av.z);
                uv.w = (xv.w - mv.w) * expf(-av.w);
                ur[idx] = uv;
                s += av.x + av.y + av.z + av.w;
            }
#pragma unroll
            for (int o = 16; o; o >>= 1) s += __shfl_down_sync(0xFFFFFFFFu, s, o);
            if (lane == 0) out[(size_t)BATCH * DIM + row] = -s;
        }
        return;
    }

    const int layer = zc >> 3;               // 0,1,2
    const int cb    = 7 - (zc & 7);          // heavy column blocks first

    // ---- per-(layer,branch) operand selection ----
    const __half* A; const __half* W; const float* bias;
    void* C; int act; bool addlast;
    if (layer == 0) {
        A = x16;                W = wm + (b ? 3 : 0) * WSZ;
        bias = b ? tb1 : sb1;   C = b ? (void*)h1t : (void*)h1s;
        act = b ? ACT_RELU : ACT_TANH;  addlast = false;
    } else if (layer == 1) {
        A = b ? h1t : h1s;      W = wm + (b ? 4 : 1) * WSZ;
        bias = b ? tb2 : sb2;   C = b ? (void*)h2t : (void*)h2s;
        act = b ? ACT_RELU : ACT_TANH;  addlast = true;
    } else {
        A = b ? h2t : h2s;      W = wm + (b ? 5 : 2) * WSZ;
        bias = b ? tb3 : sb3;   C = b ? (void*)abuf : (void*)mbuf;
        act = ACT_NONE;                 addlast = true;
    }

    const int warpM = warp >> 2;
    const int warpN = warp & 3;
    const int qr    = lane >> 2;
    const int qc    = lane & 3;

    const int rowA0 = y * 128;
    const int colB0 = cb * 128;

    // ---- wait for producing strip (layers 1,2) ----
    if (layer > 0) {
        if (tid == 0) {
            volatile unsigned* cnt = &g_done[layer - 1][b][y];
            while (*cnt < 8u) { __nanosleep(128); }
            __threadfence();
        }
        __syncthreads();
    }

    // ---- active K-chunk schedule ----
    const int Klim = min(NCH, cb * 2 + 2);
    const int NACT = (addlast && Klim < NCH) ? Klim + 1 : Klim;
#define CHUNK_OF(j) (((j) < Klim) ? (j) : (NCH - 1))

    float acc[4][4][4];
#pragma unroll
    for (int mf = 0; mf < 4; ++mf)
#pragma unroll
        for (int nf = 0; nf < 4; ++nf)
#pragma unroll
            for (int r = 0; r < 4; ++r) acc[mf][nf][r] = 0.f;

    // ---- cp.async slot bases ----
    const int r0 = tid >> 3;
    const int c  = tid & 7;
    const __half* gA = A + (size_t)(rowA0 + r0) * DIM + c * 8;
    const __half* gB = W + (size_t)(colB0 + r0) * DIM + c * 8;
    const uint32_t sA = (uint32_t)(r0 * ROWB + c * 16);
    const uint32_t sB = (uint32_t)(B_SMEM_OFF + r0 * ROWB + c * 16);

#define LOAD_CHUNK(kt, st) do {                                              \
        uint32_t _b = sbase + (uint32_t)(st) * STAGE_BYTES;                  \
        const __half* _ga = gA + (kt) * 64;                                  \
        const __half* _gb = gB + (kt) * 64;                                  \
        _Pragma("unroll")                                                    \
        for (int _i = 0; _i < 4; ++_i) {                                     \
            CP_ASYNC16(_b + sA + _i * (32 * ROWB), _ga + _i * (32 * DIM));   \
            CP_ASYNC16(_b + sB + _i * (32 * ROWB), _gb + _i * (32 * DIM));   \
        }                                                                    \
    } while (0)

    // ---- ldmatrix per-thread base offsets ----
    uint32_t aoff[4], boff[2];
#pragma unroll
    for (int mf = 0; mf < 4; ++mf) {
        int arow = warpM * 64 + mf * 16 + (lane & 15);
        aoff[mf] = (uint32_t)(arow * ROWB + ((lane >> 4) & 1) * 16);
    }
#pragma unroll
    for (int np = 0; np < 2; ++np) {
        int brow = warpN * 32 + np * 16 + (lane & 7) + ((lane >> 4) & 1) * 8;
        boff[np] = (uint32_t)(B_SMEM_OFF + brow * ROWB + ((lane >> 3) & 1) * 16);
    }

    // Prologue: prefetch active chunks 0 and 1 (NACT >= 2 always)
    LOAD_CHUNK(CHUNK_OF(0), 0); CP_COMMIT();
    LOAD_CHUNK(CHUNK_OF(1), 1); CP_COMMIT();

    int st_c = 0;
    for (int j = 0; j < NACT; ++j) {
        CP_WAIT1();
        __syncthreads();

        if (j + 2 < NACT) {
            int st_n = st_c + 2; if (st_n >= STAGES) st_n -= STAGES;
            LOAD_CHUNK(CHUNK_OF(j + 2), st_n);
        }
        CP_COMMIT();

        const uint32_t stb = sbase + (uint32_t)st_c * STAGE_BYTES;
#pragma unroll
        for (int s = 0; s < 4; ++s) {
            uint32_t afr[4][4];
            uint32_t bfr[4][2];
#pragma unroll
            for (int mf = 0; mf < 4; ++mf)
                ldm_x4(afr[mf][0], afr[mf][1], afr[mf][2], afr[mf][3],
                       stb + aoff[mf] + s * 32);
#pragma unroll
            for (int np = 0; np < 2; ++np)
                ldm_x4(bfr[2 * np][0], bfr[2 * np][1],
                       bfr[2 * np + 1][0], bfr[2 * np + 1][1],
                       stb + boff[np] + s * 32);
#pragma unroll
            for (int mf = 0; mf < 4; ++mf)
#pragma unroll
                for (int nf = 0; nf < 4; ++nf)
                    mma_f16(acc[mf][nf][0], acc[mf][nf][1], acc[mf][nf][2], acc[mf][nf][3],
                            afr[mf][0], afr[mf][1], afr[mf][2], afr[mf][3],
                            bfr[nf][0], bfr[nf][1]);
        }
        ++st_c; if (st_c >= STAGES) st_c = 0;
    }
#undef CHUNK_OF
#undef LOAD_CHUNK

    // ---- epilogue: bias + activation ----
#pragma unroll
    for (int mf = 0; mf < 4; ++mf) {
#pragma unroll
        for (int nf = 0; nf < 4; ++nf) {
            int row0 = rowA0 + warpM * 64 + mf * 16 + qr;
            int col0 = colB0 + warpN * 32 + nf * 8 + 2 * qc;
            float b0 = bias[col0];
            float b1 = bias[col0 + 1];
            float v0 = acc[mf][nf][0] + b0;
            float v1 = acc[mf][nf][1] + b1;
            float v2 = acc[mf][nf][2] + b0;
            float v3 = acc[mf][nf][3] + b1;
            if (act == ACT_TANH) {
                v0 = tanhf(v0); v1 = tanhf(v1); v2 = tanhf(v2); v3 = tanhf(v3);
            } else if (act == ACT_RELU) {
                v0 = fmaxf(v0, 0.f); v1 = fmaxf(v1, 0.f);
                v2 = fmaxf(v2, 0.f); v3 = fmaxf(v3, 0.f);
            }
            if (layer < 2) {   // __half intermediate
                __half2* p0 = reinterpret_cast<__half2*>((__half*)C + (size_t)row0 * DIM + col0);
                __half2* p1 = reinterpret_cast<__half2*>((__half*)C + (size_t)(row0 + 8) * DIM + col0);
                *p0 = __floats2half2_rn(v0, v1);
                *p1 = __floats2half2_rn(v2, v3);
            } else {            // float output (m / a)
                *reinterpret_cast<float2*>((float*)C + (size_t)row0 * DIM + col0)       = make_float2(v0, v1);
                *reinterpret_cast<float2*>((float*)C + (size_t)(row0 + 8) * DIM + col0) = make_float2(v2, v3);
            }
        }
    }

    // ---- signal completion (all layers feed a consumer now) ----
    __threadfence();
    __syncthreads();
    if (tid == 0) atomicAdd(&g_done[layer][b][y], 1u);
}

// ---------------- launcher ---------------------------------------------------
extern "C" void kernel_launch(void* const* d_in, const int* in_sizes, int n_in,
                              void* d_out, int out_size) {
    (void)in_sizes; (void)n_in; (void)out_size;
    const float* x      = (const float*)d_in[0];
    const float* s_w1   = (const float*)d_in[1];
    const float* s_b1   = (const float*)d_in[2];
    const float* s_w2   = (const float*)d_in[3];
    const float* s_b2   = (const float*)d_in[4];
    const float* s_w3   = (const float*)d_in[5];
    const float* s_b3   = (const float*)d_in[6];
    const float* t_w1   = (const float*)d_in[7];
    const float* t_b1   = (const float*)d_in[8];
    const float* t_w2   = (const float*)d_in[9];
    const float* t_b2   = (const float*)d_in[10];
    const float* t_w3   = (const float*)d_in[11];
    const float* t_b3   = (const float*)d_in[12];
    float* out = (float*)d_out;

    __half *wm, *x16, *h1s, *h2s, *h1t, *h2t;
    float *mbuf, *abuf;
    void* doneptr;
    cudaGetSymbolAddress((void**)&wm,   g_wm16);
    cudaGetSymbolAddress((void**)&x16,  g_x16);
    cudaGetSymbolAddress((void**)&h1s,  g_h1s);
    cudaGetSymbolAddress((void**)&h2s,  g_h2s);
    cudaGetSymbolAddress((void**)&h1t,  g_h1t);
    cudaGetSymbolAddress((void**)&h2t,  g_h2t);
    cudaGetSymbolAddress((void**)&mbuf, g_m);
    cudaGetSymbolAddress((void**)&abuf, g_a);
    cudaGetSymbolAddress(&doneptr, g_done);

    cudaFuncSetAttribute((const void*)gemm_made_kernel,
                         cudaFuncAttributeMaxDynamicSharedMemorySize, GEMM_SMEM);

    // reset dependency counters (graph-capturable async memset, same stream)
    cudaMemsetAsync(doneptr, 0, sizeof(unsigned) * 3 * 2 * 32, 0);

    // fused prep: blocks [0,1024) masked weights (analytic masks), [1024,5120) x
    prep_fused<<<5120, 256>>>(s_w1, s_w2, s_w3, t_w1, t_w2, t_w3, x, wm, x16);

    // One launch: 3 layers x 2 branches x 32 strips x 8 column blocks + finale.
    dim3 grid(2, BATCH / 128, 25);
    gemm_made_kernel<<<grid, 256, GEMM_SMEM>>>(
        x, x16, h1s, h1t, h2s, h2t, wm,
        s_b1, s_b2, s_b3, t_b1, t_b2, t_b3, mbuf, abuf, out);
}

// round 14
// speedup vs baseline: 1.2532x; 1.2532x over previous
#include <cuda_runtime.h>
#include <cuda_fp16.h>
#include <cstdint>
#include <cstddef>

#define BATCH 4096
#define DIM   1024

// ---------------- scratch (static device memory) ----------------------------
__device__ __half g_wm16[6u * 1024u * 1024u];  // fp16 masked weights
__device__ __half g_x16 [BATCH * DIM];         // fp16 input copy
__device__ __half g_h1s [BATCH * DIM];
__device__ __half g_h2s [BATCH * DIM];
__device__ __half g_h1t [BATCH * DIM];
__device__ __half g_h2t [BATCH * DIM];
__device__ float  g_m   [BATCH * DIM];
__device__ float  g_a   [BATCH * DIM];
__device__ unsigned g_done[2][2][32];          // [layer 0/1 done][branch][M-block]
__device__ unsigned g_prepB;                    // prepB CTAs completed (64 total)

// ---------------- helpers ---------------------------------------------------
__device__ __forceinline__ uint32_t smem_u32(const void* p) {
    uint32_t a;
    asm("{ .reg .u64 t; cvta.to.shared.u64 t, %1; cvt.u32.u64 %0, t; }" : "=r"(a) : "l"(p));
    return a;
}

__device__ __forceinline__ void ldm_x4(uint32_t& r0, uint32_t& r1, uint32_t& r2, uint32_t& r3,
                                       uint32_t addr) {
    asm volatile("ldmatrix.sync.aligned.m8n8.x4.shared.b16 {%0,%1,%2,%3}, [%4];"
                 : "=r"(r0), "=r"(r1), "=r"(r2), "=r"(r3) : "r"(addr));
}

__device__ __forceinline__ void mma_f16(float& d0, float& d1, float& d2, float& d3,
                                        uint32_t a0, uint32_t a1, uint32_t a2, uint32_t a3,
                                        uint32_t b0, uint32_t b1) {
    asm("mma.sync.aligned.m16n8k16.row.col.f32.f16.f16.f32 "
        "{%0,%1,%2,%3},{%4,%5,%6,%7},{%8,%9},{%0,%1,%2,%3};\n"
        : "+f"(d0), "+f"(d1), "+f"(d2), "+f"(d3)
        : "r"(a0), "r"(a1), "r"(a2), "r"(a3), "r"(b0), "r"(b1));
}

#define CP_ASYNC16(dst, src) \
    asm volatile("cp.async.cg.shared.global [%0], [%1], 16;" :: "r"(dst), "l"(src) : "memory")
#define CP_COMMIT() asm volatile("cp.async.commit_group;" ::: "memory")
#define CP_WAIT1()  asm volatile("cp.async.wait_group 1;" ::: "memory")

// ---------------- prepA: x conversion + layer-1 weights (slots 0,3) ----------
// mask_in[o,i] = (o%1023 >= i). Layer-0 GEMM reads only the triangular region
// (c4 < 32*(cb+1)) of slots 0,3. Also zeroes the mega-kernel sync counters.
__global__ void prep_a(const float* __restrict__ sw1, const float* __restrict__ tw1,
                       const float* __restrict__ x,
                       __half* __restrict__ dst, __half* __restrict__ xdst) {
    const size_t WSZ = 1024u * 1024u;
    const int bid = blockIdx.x;
    const int tid = threadIdx.x;
    if (bid == 0) {
        if (tid < 128) (&g_done[0][0][0])[tid] = 0u;
        else if (tid == 128) g_prepB = 0u;
    }
    if (bid >= 1024) {
        // ---- x conversion: 1 float4 per thread ----
        int i = (bid - 1024) * 256 + tid;
        float4 v = reinterpret_cast<const float4*>(x)[i];
        __half2* d2 = reinterpret_cast<__half2*>(xdst);
        d2[2 * i]     = __floats2half2_rn(v.x, v.y);
        d2[2 * i + 1] = __floats2half2_rn(v.z, v.w);
        return;
    }
    int i  = bid * 256 + tid;   // over 262144 float4
    int o  = i >> 8;            // output row
    int c4 = i & 255;           // float4 column index
    int cb = o >> 7;
    if (c4 >= 32 * (cb + 1)) return;   // outside triangular region
    const int col0 = c4 * 4;
    const int od = o % 1023;
    float mi[4];
#pragma unroll
    for (int k = 0; k < 4; ++k) mi[k] = (od >= col0 + k) ? 1.f : 0.f;
#define DO_W(wp, mk, slot) { \
        float4 wv = reinterpret_cast<const float4*>(wp)[i]; \
        __half2* d2 = reinterpret_cast<__half2*>(dst + (slot) * WSZ); \
        d2[2 * i]     = __floats2half2_rn(wv.x * mk[0], wv.y * mk[1]); \
        d2[2 * i + 1] = __floats2half2_rn(wv.z * mk[2], wv.w * mk[3]); }
    DO_W(sw1, mi, 0);
    DO_W(tw1, mi, 3);
#undef DO_W
}

// ---------------- single-launch: prepB + 3-layer dual-branch GEMM ------------
// Grid = (branch=2, M=32, zc=25); zc slowest. zc==0: prepB CTAs (64, dispatched
// FIRST, never spin) prepare weight slots 1,2,4,5 (mask_hid / mask_out,
// triangular + wrap chunk). zc>=1: zcl=zc-1, layer=zcl>>3, cb=7-(zcl&7) (LPT).
// Layer-1 tiles gate on g_prepB==64 + strip dep; layer-2 on strip dep only
// (prepB guaranteed transitively). fp16 in, fp32 acc; CTA tile 128x128, BK=64,
// 256 threads, warp tile 64x32, 3-stage cp.async (110 KB smem -> 2 CTAs/SM).
#define ACT_TANH 0
#define ACT_RELU 1
#define ACT_NONE 2

#define NCH 16
#define STAGES 3
#define ROWB 144
#define STAGE_BYTES (256 * ROWB)
#define B_SMEM_OFF  (128 * ROWB)
#define GEMM_SMEM   (STAGES * STAGE_BYTES)   // 110592

__global__ __launch_bounds__(256, 2)
void gemm_made_kernel(const __half* __restrict__ x16,
                      __half* __restrict__ h1s, __half* __restrict__ h1t,
                      __half* __restrict__ h2s, __half* __restrict__ h2t,
                      __half* __restrict__ wm,
                      const float* __restrict__ sw2, const float* __restrict__ sw3,
                      const float* __restrict__ tw2, const float* __restrict__ tw3,
                      const float* __restrict__ sb1, const float* __restrict__ sb2,
                      const float* __restrict__ sb3, const float* __restrict__ tb1,
                      const float* __restrict__ tb2, const float* __restrict__ tb3,
                      float* __restrict__ mbuf, float* __restrict__ abuf) {
    extern __shared__ __align__(16) char smc[];
    const uint32_t sbase = smem_u32(smc);
    const size_t WSZ = 1024u * 1024u;

    const int b   = blockIdx.x;            // branch
    const int y   = blockIdx.y;            // M-block
    const int zc  = blockIdx.z;

    const int tid  = threadIdx.x;
    const int warp = tid >> 5;
    const int lane = tid & 31;

    if (zc == 0) {
        // ================= prepB: weight slots 1,2,4,5 (16 rows per CTA) ====
        const int p = b * 32 + y;           // 0..63
#pragma unroll 1
        for (int r = 0; r < 16; ++r) {
            const int o   = p * 16 + r;
            const int cb  = o >> 7;
            const int lim = 32 * (cb + 1);
            const int od  = o % 1023;
            const int total = (cb == 7) ? 256 : (lim + 16);
            for (int t = tid; t < total; t += 256) {
                const int c4 = (t < lim) ? t : (240 + (t - lim));
                const size_t i = ((size_t)o << 8) + c4;
                const int col0 = c4 * 4;
                float mh[4], mo[4];
#pragma unroll
                for (int k = 0; k < 4; ++k) {
                    int cm = (col0 + k) % 1023;
                    mh[k] = (od >= cm)      ? 1.f : 0.f;
                    mo[k] = ((o - 1) >= cm) ? 1.f : 0.f;
                }
#define DO_W(wp, mk, slot) { \
                float4 wv = reinterpret_cast<const float4*>(wp)[i]; \
                __half2* d2 = reinterpret_cast<__half2*>(wm + (slot) * WSZ); \
                d2[2 * i]     = __floats2half2_rn(wv.x * mk[0], wv.y * mk[1]); \
                d2[2 * i + 1] = __floats2half2_rn(wv.z * mk[2], wv.w * mk[3]); }
                DO_W(sw2, mh, 1); DO_W(sw3, mo, 2);
                DO_W(tw2, mh, 4); DO_W(tw3, mo, 5);
#undef DO_W
            }
        }
        __threadfence();
        __syncthreads();
        if (tid == 0) atomicAdd(&g_prepB, 1u);
        return;
    }

    const int zcl   = zc - 1;
    const int layer = zcl >> 3;               // 0,1,2
    const int cb    = 7 - (zcl & 7);          // heavy column blocks first

    // ---- per-(layer,branch) operand selection ----
    const __half* A; const __half* W; const float* bias;
    void* C; int act; bool addlast;
    if (layer == 0) {
        A = x16;                W = wm + (b ? 3 : 0) * WSZ;
        bias = b ? tb1 : sb1;   C = b ? (void*)h1t : (void*)h1s;
        act = b ? ACT_RELU : ACT_TANH;  addlast = false;
    } else if (layer == 1) {
        A = b ? h1t : h1s;      W = wm + (b ? 4 : 1) * WSZ;
        bias = b ? tb2 : sb2;   C = b ? (void*)h2t : (void*)h2s;
        act = b ? ACT_RELU : ACT_TANH;  addlast = true;
    } else {
        A = b ? h2t : h2s;      W = wm + (b ? 5 : 2) * WSZ;
        bias = b ? tb3 : sb3;   C = b ? (void*)abuf : (void*)mbuf;
        act = ACT_NONE;                 addlast = true;
    }

    const int warpM = warp >> 2;
    const int warpN = warp & 3;
    const int qr    = lane >> 2;
    const int qc    = lane & 3;

    const int rowA0 = y * 128;
    const int colB0 = cb * 128;

    // ---- wait for producers ----
    if (layer == 1) {
        if (tid == 0) {
            volatile unsigned* pb = &g_prepB;
            while (*pb < 64u) { __nanosleep(128); }
            volatile unsigned* cnt = &g_done[0][b][y];
            while (*cnt < 8u) { __nanosleep(128); }
            __threadfence();
        }
        __syncthreads();
    } else if (layer == 2) {
        if (tid == 0) {
            volatile unsigned* cnt = &g_done[1][b][y];
            while (*cnt < 8u) { __nanosleep(128); }
            __threadfence();
        }
        __syncthreads();
    }

    // ---- active K-chunk schedule ----
    const int Klim = min(NCH, cb * 2 + 2);
    const int NACT = (addlast && Klim < NCH) ? Klim + 1 : Klim;
#define CHUNK_OF(j) (((j) < Klim) ? (j) : (NCH - 1))

    float acc[4][4][4];
#pragma unroll
    for (int mf = 0; mf < 4; ++mf)
#pragma unroll
        for (int nf = 0; nf < 4; ++nf)
#pragma unroll
            for (int r = 0; r < 4; ++r) acc[mf][nf][r] = 0.f;

    // ---- cp.async slot bases ----
    const int r0 = tid >> 3;
    const int c  = tid & 7;
    const __half* gA = A + (size_t)(rowA0 + r0) * DIM + c * 8;
    const __half* gB = W + (size_t)(colB0 + r0) * DIM + c * 8;
    const uint32_t sA = (uint32_t)(r0 * ROWB + c * 16);
    const uint32_t sB = (uint32_t)(B_SMEM_OFF + r0 * ROWB + c * 16);

#define LOAD_CHUNK(kt, st) do {                                              \
        uint32_t _b = sbase + (uint32_t)(st) * STAGE_BYTES;                  \
        const __half* _ga = gA + (kt) * 64;                                  \
        const __half* _gb = gB + (kt) * 64;                                  \
        _Pragma("unroll")                                                    \
        for (int _i = 0; _i < 4; ++_i) {                                     \
            CP_ASYNC16(_b + sA + _i * (32 * ROWB), _ga + _i * (32 * DIM));   \
            CP_ASYNC16(_b + sB + _i * (32 * ROWB), _gb + _i * (32 * DIM));   \
        }                                                                    \
    } while (0)

    // ---- ldmatrix per-thread base offsets ----
    uint32_t aoff[4], boff[2];
#pragma unroll
    for (int mf = 0; mf < 4; ++mf) {
        int arow = warpM * 64 + mf * 16 + (lane & 15);
        aoff[mf] = (uint32_t)(arow * ROWB + ((lane >> 4) & 1) * 16);
    }
#pragma unroll
    for (int np = 0; np < 2; ++np) {
        int brow = warpN * 32 + np * 16 + (lane & 7) + ((lane >> 4) & 1) * 8;
        boff[np] = (uint32_t)(B_SMEM_OFF + brow * ROWB + ((lane >> 3) & 1) * 16);
    }

    // Prologue: prefetch active chunks 0 and 1 (NACT >= 2 always)
    LOAD_CHUNK(CHUNK_OF(0), 0); CP_COMMIT();
    LOAD_CHUNK(CHUNK_OF(1), 1); CP_COMMIT();

    int st_c = 0;
    for (int j = 0; j < NACT; ++j) {
        CP_WAIT1();
        __syncthreads();

        if (j + 2 < NACT) {
            int st_n = st_c + 2; if (st_n >= STAGES) st_n -= STAGES;
            LOAD_CHUNK(CHUNK_OF(j + 2), st_n);
        }
        CP_COMMIT();

        const uint32_t stb = sbase + (uint32_t)st_c * STAGE_BYTES;
#pragma unroll
        for (int s = 0; s < 4; ++s) {
            uint32_t afr[4][4];
            uint32_t bfr[4][2];
#pragma unroll
            for (int mf = 0; mf < 4; ++mf)
                ldm_x4(afr[mf][0], afr[mf][1], afr[mf][2], afr[mf][3],
                       stb + aoff[mf] + s * 32);
#pragma unroll
            for (int np = 0; np < 2; ++np)
                ldm_x4(bfr[2 * np][0], bfr[2 * np][1],
                       bfr[2 * np + 1][0], bfr[2 * np + 1][1],
                       stb + boff[np] + s * 32);
#pragma unroll
            for (int mf = 0; mf < 4; ++mf)
#pragma unroll
                for (int nf = 0; nf < 4; ++nf)
                    mma_f16(acc[mf][nf][0], acc[mf][nf][1], acc[mf][nf][2], acc[mf][nf][3],
                            afr[mf][0], afr[mf][1], afr[mf][2], afr[mf][3],
                            bfr[nf][0], bfr[nf][1]);
        }
        ++st_c; if (st_c >= STAGES) st_c = 0;
    }
#undef CHUNK_OF
#undef LOAD_CHUNK

    // ---- epilogue: bias + activation ----
#pragma unroll
    for (int mf = 0; mf < 4; ++mf) {
#pragma unroll
        for (int nf = 0; nf < 4; ++nf) {
            int row0 = rowA0 + warpM * 64 + mf * 16 + qr;
            int col0 = colB0 + warpN * 32 + nf * 8 + 2 * qc;
            float b0 = bias[col0];
            float b1 = bias[col0 + 1];
            float v0 = acc[mf][nf][0] + b0;
            float v1 = acc[mf][nf][1] + b1;
            float v2 = acc[mf][nf][2] + b0;
            float v3 = acc[mf][nf][3] + b1;
            if (act == ACT_TANH) {
                v0 = tanhf(v0); v1 = tanhf(v1); v2 = tanhf(v2); v3 = tanhf(v3);
            } else if (act == ACT_RELU) {
                v0 = fmaxf(v0, 0.f); v1 = fmaxf(v1, 0.f);
                v2 = fmaxf(v2, 0.f); v3 = fmaxf(v3, 0.f);
            }
            if (layer < 2) {   // __half intermediate
                __half2* p0 = reinterpret_cast<__half2*>((__half*)C + (size_t)row0 * DIM + col0);
                __half2* p1 = reinterpret_cast<__half2*>((__half*)C + (size_t)(row0 + 8) * DIM + col0);
                *p0 = __floats2half2_rn(v0, v1);
                *p1 = __floats2half2_rn(v2, v3);
            } else {            // float output (m / a)
                *reinterpret_cast<float2*>((float*)C + (size_t)row0 * DIM + col0)       = make_float2(v0, v1);
                *reinterpret_cast<float2*>((float*)C + (size_t)(row0 + 8) * DIM + col0) = make_float2(v2, v3);
            }
        }
    }

    // ---- signal completion (layers 0,1 feed a consumer) ----
    if (layer < 2) {
        __threadfence();
        __syncthreads();
        if (tid == 0) atomicAdd(&g_done[layer][b][y], 1u);
    }
}

// ---------------- final elementwise + logdet (vectorized) --------------------
__global__ void final_kernel(const float* __restrict__ x, const float* __restrict__ m,
                             const float* __restrict__ a, float* __restrict__ out) {
    int b = blockIdx.x;
    int t = threadIdx.x;
    size_t base4 = (size_t)b * (DIM / 4) + t;   // float4 index
    float4 av = reinterpret_cast<const float4*>(a)[base4];
    float4 mv = reinterpret_cast<const float4*>(m)[base4];
    float4 xv = reinterpret_cast<const float4*>(x)[base4];
    float4 uv;
    uv.x = (xv.x - mv.x) * expf(-av.x);
    uv.y = (xv.y - mv.y) * expf(-av.y);
    uv.z = (xv.z - mv.z) * expf(-av.z);
    uv.w = (xv.w - mv.w) * expf(-av.w);
    reinterpret_cast<float4*>(out)[base4] = uv;
    float s = av.x + av.y + av.z + av.w;
#pragma unroll
    for (int o = 16; o; o >>= 1) s += __shfl_down_sync(0xFFFFFFFFu, s, o);
    __shared__ float ws[8];
    if ((t & 31) == 0) ws[t >> 5] = s;
    __syncthreads();
    if (t < 8) {
        float v = ws[t];
#pragma unroll
        for (int o = 4; o; o >>= 1) v += __shfl_down_sync(0xFFu, v, o);
        if (t == 0) out[(size_t)BATCH * DIM + b] = -v;
    }
}

// ---------------- launcher ---------------------------------------------------
extern "C" void kernel_launch(void* const* d_in, const int* in_sizes, int n_in,
                              void* d_out, int out_size) {
    (void)in_sizes; (void)n_in; (void)out_size;
    const float* x      = (const float*)d_in[0];
    const float* s_w1   = (const float*)d_in[1];
    const float* s_b1   = (const float*)d_in[2];
    const float* s_w2   = (const float*)d_in[3];
    const float* s_b2   = (const float*)d_in[4];
    const float* s_w3   = (const float*)d_in[5];
    const float* s_b3   = (const float*)d_in[6];
    const float* t_w1   = (const float*)d_in[7];
    const float* t_b1   = (const float*)d_in[8];
    const float* t_w2   = (const float*)d_in[9];
    const float* t_b2   = (const float*)d_in[10];
    const float* t_w3   = (const float*)d_in[11];
    const float* t_b3   = (const float*)d_in[12];
    float* out = (float*)d_out;

    __half *wm, *x16, *h1s, *h2s, *h1t, *h2t;
    float *mbuf, *abuf;
    cudaGetSymbolAddress((void**)&wm,   g_wm16);
    cudaGetSymbolAddress((void**)&x16,  g_x16);
    cudaGetSymbolAddress((void**)&h1s,  g_h1s);
    cudaGetSymbolAddress((void**)&h2s,  g_h2s);
    cudaGetSymbolAddress((void**)&h1t,  g_h1t);
    cudaGetSymbolAddress((void**)&h2t,  g_h2t);
    cudaGetSymbolAddress((void**)&mbuf, g_m);
    cudaGetSymbolAddress((void**)&abuf, g_a);

    cudaFuncSetAttribute((const void*)gemm_made_kernel,
                         cudaFuncAttributeMaxDynamicSharedMemorySize, GEMM_SMEM);

    // prepA: counter reset + x convert + layer-1 weights (slots 0,3)
    prep_a<<<5120, 256>>>(s_w1, t_w1, x, wm, x16);

    // One launch: prepB (zc=0, dispatched first) + 3 layers x 2 branches.
    dim3 grid(2, BATCH / 128, 25);
    gemm_made_kernel<<<grid, 256, GEMM_SMEM>>>(
        x16, h1s, h1t, h2s, h2t, wm,
        s_w2, s_w3, t_w2, t_w3,
        s_b1, s_b2, s_b3, t_b1, t_b2, t_b3, mbuf, abuf);

    final_kernel<<<BATCH, 256>>>(x, mbuf, abuf, out);
}